// round 7
// baseline (speedup 1.0000x reference)
#include <cuda_runtime.h>

#define Bn 64
#define Nn 4096
#define Kk 11
#define KP 12
#define Dd 192
#define HIDn 128
#define Tt 128
#define XST 196
#define EPSF 1e-8f
#define LN_EPSF 1e-5f
#define SCALEF 0.07216878364870323f

typedef unsigned long long ull;

__device__ __forceinline__ ull pk2(float x) {
    ull r; asm("mov.b64 %0, {%1, %1};" : "=l"(r) : "f"(x)); return r;
}
__device__ __forceinline__ ull f2fma(ull a, ull b, ull c) {
    ull d; asm("fma.rn.f32x2 %0, %1, %2, %3;" : "=l"(d) : "l"(a), "l"(b), "l"(c)); return d;
}
__device__ __forceinline__ ull f2add(ull a, ull b) {
    ull d; asm("add.rn.f32x2 %0, %1, %2;" : "=l"(d) : "l"(a), "l"(b)); return d;
}
__device__ __forceinline__ float2 up2(ull v) {
    float lo, hi; asm("mov.b64 {%0, %1}, %2;" : "=f"(lo), "=f"(hi) : "l"(v));
    return make_float2(lo, hi);
}
__device__ __forceinline__ void fma12(ull acc[6], const float* p, ull xx) {
    ulonglong2 q0 = *(const ulonglong2*)p;
    ulonglong2 q1 = *(const ulonglong2*)(p + 4);
    ulonglong2 q2 = *(const ulonglong2*)(p + 8);
    acc[0] = f2fma(q0.x, xx, acc[0]); acc[1] = f2fma(q0.y, xx, acc[1]);
    acc[2] = f2fma(q1.x, xx, acc[2]); acc[3] = f2fma(q1.y, xx, acc[3]);
    acc[4] = f2fma(q2.x, xx, acc[4]); acc[5] = f2fma(q2.y, xx, acc[5]);
}
// unpack 6 f32x2 accumulators into 11 floats (+pad discarded)
__device__ __forceinline__ void unpk11(const ull a6[6], float* o) {
#pragma unroll
    for (int j = 0; j < 6; j++) {
        float2 f = up2(a6[j]);
        o[2 * j] = f.x;
        if (2 * j + 1 < Kk) o[2 * j + 1] = f.y;
    }
}

__device__ float g_slots[Bn * Kk * Dd];
__device__ float g_w2k[Bn * Kk * Dd];
__device__ float g_w2sum[Bn * Kk];
__device__ float g_cc[Bn * Kk];
__device__ float g_R[Bn * Kk * Dd];
__device__ float g_s1[Bn * Kk];
__device__ float g_s2[Bn * Kk];
__device__ float g_WqT[Dd * Dd];     // [t][e]
__device__ float g_WvT[Dd * Dd];     // [t][e]
__device__ float g_W1T[HIDn * Dd];   // [t][e]
__device__ float g_W2T[Dd * HIDn];   // [t][h]

// ---------------- init ----------------
__global__ void k_init(const float* __restrict__ noise, const float* __restrict__ smu,
                       const float* __restrict__ ssig, const float* __restrict__ Wq,
                       const float* __restrict__ Wv, const float* __restrict__ W1,
                       const float* __restrict__ W2) {
    const int T0 = Bn * Kk * Dd;
    const int T1 = T0 + Dd * Dd;
    const int T2 = T1 + Dd * Dd;
    const int T3 = T2 + Dd * HIDn;
    const int T4 = T3 + HIDn * Dd;
    for (int i = blockIdx.x * blockDim.x + threadIdx.x; i < T4; i += gridDim.x * blockDim.x) {
        if (i < T0) { int d = i % Dd; g_slots[i] = smu[d] + ssig[d] * noise[i]; }
        else if (i < T1) { int i2 = i - T0; g_WqT[(i2 % Dd) * Dd + i2 / Dd] = Wq[i2]; }
        else if (i < T2) { int i2 = i - T1; g_WvT[(i2 % Dd) * Dd + i2 / Dd] = Wv[i2]; }
        else if (i < T3) { int i2 = i - T2; g_W1T[(i2 % HIDn) * Dd + i2 / HIDn] = W1[i2]; }
        else { int i2 = i - T3; g_W2T[(i2 % Dd) * HIDn + i2 / Dd] = W2[i2]; }
    }
}

// ---------------- iter-0 slot preprocessing ----------------
__global__ __launch_bounds__(192) void k_pre(const float* __restrict__ lnw_s,
                                             const float* __restrict__ lnb_s,
                                             const float* __restrict__ bq,
                                             const float* __restrict__ Wk,
                                             const float* __restrict__ bk,
                                             const float* __restrict__ lnw_in,
                                             const float* __restrict__ lnb_in) {
    __shared__ float snt[Dd * KP];
    __shared__ float qT[Dd * KP];
    __shared__ float red[24];
    int b = blockIdx.x, t = threadIdx.x, wid = t >> 5, lane = t & 31;
    if (t < 24) red[t] = 0.f;
    snt[t * KP + 11] = 0.f;

    for (int r = wid; r < Kk; r += 6) {
        float v[6], s = 0.f;
#pragma unroll
        for (int i = 0; i < 6; i++) { v[i] = g_slots[(b * Kk + r) * Dd + lane + 32 * i]; s += v[i]; }
#pragma unroll
        for (int o = 16; o; o >>= 1) s += __shfl_xor_sync(~0u, s, o);
        float mu = s * (1.0f / Dd), q = 0.f;
#pragma unroll
        for (int i = 0; i < 6; i++) { float d = v[i] - mu; q += d * d; }
#pragma unroll
        for (int o = 16; o; o >>= 1) q += __shfl_xor_sync(~0u, q, o);
        float rstd = rsqrtf(q * (1.0f / Dd) + LN_EPSF);
#pragma unroll
        for (int i = 0; i < 6; i++) {
            int d = lane + 32 * i;
            snt[d * KP + r] = (v[i] - mu) * rstd * lnw_s[d] + lnb_s[d];
        }
    }
    __syncthreads();

    ull a6[6];
#pragma unroll
    for (int j = 0; j < 6; j++) a6[j] = 0ull;
    {
        const float4* w4 = (const float4*)(g_WqT + t * Dd);
#pragma unroll 4
        for (int c = 0; c < 48; c++) {
            float4 w = __ldg(&w4[c]);
            fma12(a6, &snt[(4 * c + 0) * KP], pk2(w.x));
            fma12(a6, &snt[(4 * c + 1) * KP], pk2(w.y));
            fma12(a6, &snt[(4 * c + 2) * KP], pk2(w.z));
            fma12(a6, &snt[(4 * c + 3) * KP], pk2(w.w));
        }
    }
    float qa[Kk];
    unpk11(a6, qa);
    float bqv = bq[t];
#pragma unroll
    for (int r = 0; r < Kk; r++) { qa[r] += bqv; qT[t * KP + r] = qa[r]; }
    qT[t * KP + 11] = 0.f;
    __syncthreads();

#pragma unroll
    for (int j = 0; j < 6; j++) a6[j] = 0ull;
    {
        const float4* w4 = (const float4*)(Wk + t * Dd);
#pragma unroll 4
        for (int c = 0; c < 48; c++) {
            float4 w = __ldg(&w4[c]);
            fma12(a6, &qT[(4 * c + 0) * KP], pk2(w.x));
            fma12(a6, &qT[(4 * c + 1) * KP], pk2(w.y));
            fma12(a6, &qT[(4 * c + 2) * KP], pk2(w.z));
            fma12(a6, &qT[(4 * c + 3) * KP], pk2(w.w));
        }
    }
    float qt[Kk];
    unpk11(a6, qt);
    float lwv = lnw_in[t], lbv = lnb_in[t], bkv = bk[t];
    float ws[Kk], cp[Kk];
#pragma unroll
    for (int r = 0; r < Kk; r++) {
        float w2 = qt[r] * SCALEF * lwv;
        g_w2k[(b * Kk + r) * Dd + t] = w2;
        ws[r] = w2;
        cp[r] = (lbv * qt[r] + qa[r] * bkv) * SCALEF;
    }
#pragma unroll
    for (int r = 0; r < Kk; r++) {
        float a = ws[r], c = cp[r];
#pragma unroll
        for (int o = 16; o; o >>= 1) {
            a += __shfl_xor_sync(~0u, a, o);
            c += __shfl_xor_sync(~0u, c, o);
        }
        if (lane == 0) { atomicAdd(&red[r], a); atomicAdd(&red[12 + r], c); }
    }
    __syncthreads();
    if (t < Kk) {
        g_w2sum[b * Kk + t] = red[t];
        g_cc[b * Kk + t] = red[12 + t];
        g_s1[b * Kk + t] = 0.f;
        g_s2[b * Kk + t] = 0.f;
    }
    for (int i = t; i < Kk * Dd; i += 192) g_R[b * Kk * Dd + i] = 0.f;
}

// ---------------- attention pass ----------------
__global__ __launch_bounds__(128) void k_attn(const float* __restrict__ x,
                                              float* __restrict__ attn_out, int wr) {
    extern __shared__ float sm[];
    float* Xs = sm;
    float* Ws = sm + Tt * XST;
    float* A1 = Ws;
    int b = blockIdx.y, tid = threadIdx.x, lane = tid & 31;
    int n0 = blockIdx.x * Tt;

    const float* xb = x + ((size_t)(b * Nn + n0)) * Dd;
    for (int i = tid * 4; i < Tt * Dd; i += 128 * 4) {
        float4 v = __ldcs((const float4*)(xb + i));
        int t = i / Dd, d = i - t * Dd;
        *(float4*)&Xs[t * XST + d] = v;
    }
    const float* wsrc = g_w2k + b * Kk * Dd;
    for (int i = tid; i < Kk * Dd; i += 128) Ws[i] = wsrc[i];
    __syncthreads();

    ull aA[Kk], aB[Kk];
#pragma unroll
    for (int k = 0; k < Kk; k++) { aA[k] = 0ull; aB[k] = 0ull; }
    ull sSa = 0ull, sSb = 0ull, sQa = 0ull, sQb = 0ull;
    const ulonglong2* xr2 = (const ulonglong2*)(Xs + tid * XST);
#pragma unroll 4
    for (int c = 0; c < 48; c++) {
        ulonglong2 xv = xr2[c];
        sSa = f2add(sSa, xv.x); sSb = f2add(sSb, xv.y);
        sQa = f2fma(xv.x, xv.x, sQa); sQb = f2fma(xv.y, xv.y, sQb);
#pragma unroll
        for (int k = 0; k < Kk; k++) {
            ulonglong2 wv = *(const ulonglong2*)&Ws[k * Dd + c * 4];
            aA[k] = f2fma(xv.x, wv.x, aA[k]);
            aB[k] = f2fma(xv.y, wv.y, aB[k]);
        }
    }
    float2 sf = up2(f2add(sSa, sSb));
    float2 qf = up2(f2add(sQa, sQb));
    float mu = (sf.x + sf.y) * (1.0f / Dd);
    float ex2 = (qf.x + qf.y) * (1.0f / Dd);
    float rs = rsqrtf(ex2 - mu * mu + LN_EPSF);
    float rm = rs * mu;
    float dk[Kk];
#pragma unroll
    for (int k = 0; k < Kk; k++) {
        float2 fa = up2(aA[k]), fb = up2(aB[k]);
        float dot = (fa.x + fa.y) + (fb.x + fb.y);
        dk[k] = rs * dot - rm * __ldg(&g_w2sum[b * Kk + k]) + __ldg(&g_cc[b * Kk + k]);
    }
    float mx = dk[0];
#pragma unroll
    for (int k = 1; k < Kk; k++) mx = fmaxf(mx, dk[k]);
    float sum = 0.f;
#pragma unroll
    for (int k = 0; k < Kk; k++) { dk[k] = __expf(dk[k] - mx); sum += dk[k]; }
    float inv = __fdividef(1.0f, sum);
#pragma unroll
    for (int k = 0; k < Kk; k++) dk[k] = fmaf(dk[k], inv, EPSF);
    int n = n0 + tid;
    if (wr) {
#pragma unroll
        for (int k = 0; k < Kk; k++)
            attn_out[((size_t)(b * Kk + k)) * Nn + n] = dk[k];
    }
#pragma unroll
    for (int k = 0; k < Kk; k++) {
        float s1v = dk[k], s2v = dk[k] * rm;
#pragma unroll
        for (int o = 16; o; o >>= 1) {
            s1v += __shfl_xor_sync(~0u, s1v, o);
            s2v += __shfl_xor_sync(~0u, s2v, o);
        }
        if (lane == 0) {
            atomicAdd(&g_s1[b * Kk + k], s1v);
            atomicAdd(&g_s2[b * Kk + k], s2v);
        }
    }
    __syncthreads();
#pragma unroll
    for (int k = 0; k < Kk; k++) A1[tid * KP + k] = dk[k] * rs;
    A1[tid * KP + 11] = 0.f;
    __syncthreads();

    for (int d = tid; d < Dd; d += 128) {
        ull c6[6];
#pragma unroll
        for (int j = 0; j < 6; j++) c6[j] = 0ull;
#pragma unroll 4
        for (int t = 0; t < Tt; t++) {
            fma12(c6, &A1[t * KP], pk2(Xs[t * XST + d]));
        }
#pragma unroll
        for (int j = 0; j < 6; j++) {
            float2 f = up2(c6[j]);
            atomicAdd(&g_R[(b * Kk + 2 * j) * Dd + d], f.x);
            if (2 * j + 1 < Kk) atomicAdd(&g_R[(b * Kk + 2 * j + 1) * Dd + d], f.y);
        }
    }
}

// ---------------- fused slot update: u->v->GRU->LN->MLP->residual->pre(next) ----
// dyn smem layout (floats):
#define S_UT   0            // Dd*KP : u / later slots_new
#define S_SPT  2304         // Dd*KP : slots_prev / later sn (LN of new slots)
#define S_VT   4608         // Dd*KP : v
#define S_P0   6912         // Dd*KP : r-gate pre / MLP1 partial / qT
#define S_P1   9216         // Dd*KP : z-gate pre / MLP1 partial
#define S_PXN  11520        // Dd*KP : n-gate x part / MLP1 partial
#define S_PHN  13824        // Dd*KP : n-gate h part
#define S_HT   16128        // Dd*KP : h (residual)
#define S_HN   18432        // Dd*KP : LN(h)
#define S_M1   20736        // HIDn*KP : MLP hidden
#define S_VP0  22272        // Dd*KP : v partial 1
#define S_VP1  24576        // Dd*KP : v partial 2
#define SLOT_SMEM_FLOATS 26880

__global__ __launch_bounds__(576) void k_slot(
    const float* __restrict__ bv,
    const float* __restrict__ Wih, const float* __restrict__ Whh,
    const float* __restrict__ bih, const float* __restrict__ bhh,
    const float* __restrict__ lnw_in, const float* __restrict__ lnb_in,
    const float* __restrict__ lnw_m, const float* __restrict__ lnb_m,
    const float* __restrict__ b1, const float* __restrict__ b2,
    const float* __restrict__ lnw_s, const float* __restrict__ lnb_s,
    const float* __restrict__ bq, const float* __restrict__ Wk,
    const float* __restrict__ bk,
    float* __restrict__ slots_out, int last) {
    extern __shared__ float sm[];
    float* uT = sm + S_UT;
    float* spT = sm + S_SPT;
    float* vT = sm + S_VT;
    float* P0 = sm + S_P0;
    float* P1 = sm + S_P1;
    float* PXn = sm + S_PXN;
    float* PHn = sm + S_PHN;
    float* hT = sm + S_HT;
    float* hN = sm + S_HN;
    float* m1 = sm + S_M1;
    float* vP0 = sm + S_VP0;
    float* vP1 = sm + S_VP1;
    __shared__ float sv[Kk], s2s[Kk], red[24];

    int b = blockIdx.x, tid = threadIdx.x;
    int wid = tid >> 5, lane = tid & 31;

    // ---- stage 0: u, slots_prev into smem; pads ----
    if (tid < Kk) {
        sv[tid] = __fdividef(1.0f, g_s1[b * Kk + tid]);
        s2s[tid] = g_s2[b * Kk + tid];
    }
    if (tid >= 32 && tid < 56) red[tid - 32] = 0.f;
    __syncthreads();
    for (int d = tid; d < Dd; d += 576) {
        uT[d * KP + 11] = 0.f; spT[d * KP + 11] = 0.f; vT[d * KP + 11] = 0.f;
        hN[d * KP + 11] = 0.f;
    }
    for (int i = tid; i < Kk * Dd; i += 576) {
        int r = i / Dd, d = i - r * Dd;
        float R = g_R[b * Kk * Dd + i];
        uT[d * KP + r] = lnw_in[d] * (R - s2s[r]) * sv[r] + lnb_in[d];
        spT[d * KP + r] = g_slots[b * Kk * Dd + i];
    }
    __syncthreads();

    // ---- stage 1: v = u @ Wv + bv, 3-way split over e ----
    {
        int p = tid / Dd, t = tid - p * Dd;   // p in 0..2
        ull a6[6];
#pragma unroll
        for (int j = 0; j < 6; j++) a6[j] = 0ull;
        const float4* w4 = (const float4*)(g_WvT + t * Dd + p * 64);
        const float* uu = uT + p * 64 * KP;
#pragma unroll 4
        for (int c = 0; c < 16; c++) {
            float4 w = __ldg(&w4[c]);
            fma12(a6, &uu[(4 * c + 0) * KP], pk2(w.x));
            fma12(a6, &uu[(4 * c + 1) * KP], pk2(w.y));
            fma12(a6, &uu[(4 * c + 2) * KP], pk2(w.z));
            fma12(a6, &uu[(4 * c + 3) * KP], pk2(w.w));
        }
        float vv[Kk];
        unpk11(a6, vv);
        float* dst = (p == 0) ? vT : (p == 1 ? vP0 : vP1);
        float bb = (p == 0) ? bv[t] : 0.f;
#pragma unroll
        for (int r = 0; r < Kk; r++) dst[t * KP + r] = vv[r] + bb;
        if (p > 0) dst[t * KP + 11] = 0.f;
    }
    __syncthreads();
    for (int i = tid; i < Dd * KP; i += 576) vT[i] += vP0[i] + vP1[i];
    __syncthreads();

    // ---- stage 2: GRU gate pre-activations, one column per thread ----
    {
        int j = tid;                   // 0..575
        int g = j / Dd, t = j - g * Dd;
        ull ax6[6], ah6[6];
#pragma unroll
        for (int jj = 0; jj < 6; jj++) { ax6[jj] = 0ull; ah6[jj] = 0ull; }
        const float4* wi4 = (const float4*)(Wih + j * Dd);
        const float4* wh4 = (const float4*)(Whh + j * Dd);
#pragma unroll 4
        for (int c = 0; c < 48; c++) {
            float4 wi = __ldg(&wi4[c]);
            float4 wh = __ldg(&wh4[c]);
            fma12(ax6, &vT[(4 * c + 0) * KP], pk2(wi.x));
            fma12(ax6, &vT[(4 * c + 1) * KP], pk2(wi.y));
            fma12(ax6, &vT[(4 * c + 2) * KP], pk2(wi.z));
            fma12(ax6, &vT[(4 * c + 3) * KP], pk2(wi.w));
            fma12(ah6, &spT[(4 * c + 0) * KP], pk2(wh.x));
            fma12(ah6, &spT[(4 * c + 1) * KP], pk2(wh.y));
            fma12(ah6, &spT[(4 * c + 2) * KP], pk2(wh.z));
            fma12(ah6, &spT[(4 * c + 3) * KP], pk2(wh.w));
        }
        float axf[Kk], ahf[Kk];
        unpk11(ax6, axf); unpk11(ah6, ahf);
        float bi = bih[j], bh = bhh[j];
        if (g == 0) {
#pragma unroll
            for (int r = 0; r < Kk; r++) P0[t * KP + r] = axf[r] + ahf[r] + bi + bh;
        } else if (g == 1) {
#pragma unroll
            for (int r = 0; r < Kk; r++) P1[t * KP + r] = axf[r] + ahf[r] + bi + bh;
        } else {
#pragma unroll
            for (int r = 0; r < Kk; r++) { PXn[t * KP + r] = axf[r] + bi; PHn[t * KP + r] = ahf[r] + bh; }
        }
    }
    __syncthreads();

    // ---- stage 3: h = (1-z)n + z*s ----
    for (int i = tid; i < Dd * Kk; i += 576) {
        int t = i / Kk, r = i - t * Kk;
        float rg = 1.0f / (1.0f + __expf(-P0[t * KP + r]));
        float zg = 1.0f / (1.0f + __expf(-P1[t * KP + r]));
        float ng = tanhf(fmaf(rg, PHn[t * KP + r], PXn[t * KP + r]));
        hT[t * KP + r] = (1.0f - zg) * ng + zg * spT[t * KP + r];
    }
    __syncthreads();

    // ---- LN(h) -> hN, warp-per-slot ----
    if (wid < Kk) {
        int r = wid;
        float v[6], s = 0.f;
#pragma unroll
        for (int i = 0; i < 6; i++) { v[i] = hT[(lane + 32 * i) * KP + r]; s += v[i]; }
#pragma unroll
        for (int o = 16; o; o >>= 1) s += __shfl_xor_sync(~0u, s, o);
        float mu = s * (1.0f / Dd), q = 0.f;
#pragma unroll
        for (int i = 0; i < 6; i++) { float d = v[i] - mu; q += d * d; }
#pragma unroll
        for (int o = 16; o; o >>= 1) q += __shfl_xor_sync(~0u, q, o);
        float rstd = rsqrtf(q * (1.0f / Dd) + LN_EPSF);
#pragma unroll
        for (int i = 0; i < 6; i++) {
            int d = lane + 32 * i;
            hN[d * KP + r] = (v[i] - mu) * rstd * lnw_m[d] + lnb_m[d];
        }
    }
    __syncthreads();

    // ---- stage 4: MLP1 (relu(hN @ W1 + b1)), 4-way split over e ----
    if (tid < 512) {
        int p = tid >> 7, t = tid & 127;
        ull a6[6];
#pragma unroll
        for (int j = 0; j < 6; j++) a6[j] = 0ull;
        const float4* w4 = (const float4*)(g_W1T + t * Dd + p * 48);
        const float* hh = hN + p * 48 * KP;
#pragma unroll 4
        for (int c = 0; c < 12; c++) {
            float4 w = __ldg(&w4[c]);
            fma12(a6, &hh[(4 * c + 0) * KP], pk2(w.x));
            fma12(a6, &hh[(4 * c + 1) * KP], pk2(w.y));
            fma12(a6, &hh[(4 * c + 2) * KP], pk2(w.z));
            fma12(a6, &hh[(4 * c + 3) * KP], pk2(w.w));
        }
        float vv[Kk];
        unpk11(a6, vv);
        float* dst = (p == 0) ? m1 : (p == 1 ? P0 : (p == 2 ? P1 : PXn));
        float bb = (p == 0) ? b1[t] : 0.f;
#pragma unroll
        for (int r = 0; r < Kk; r++) dst[t * KP + r] = vv[r] + bb;
        dst[t * KP + 11] = 0.f;
    }
    __syncthreads();
    for (int i = tid; i < HIDn * KP; i += 576)
        m1[i] = fmaxf(m1[i] + P0[i] + P1[i] + PXn[i], 0.0f);
    __syncthreads();

    // ---- stage 5: slots_new = h + m1 @ W2 + b2 -> uT (reuse) + global ----
    if (tid < Dd) {
        int t = tid;
        ull a6[6];
#pragma unroll
        for (int j = 0; j < 6; j++) a6[j] = 0ull;
        const float4* w4 = (const float4*)(g_W2T + t * HIDn);
#pragma unroll 4
        for (int c = 0; c < 32; c++) {
            float4 w = __ldg(&w4[c]);
            fma12(a6, &m1[(4 * c + 0) * KP], pk2(w.x));
            fma12(a6, &m1[(4 * c + 1) * KP], pk2(w.y));
            fma12(a6, &m1[(4 * c + 2) * KP], pk2(w.z));
            fma12(a6, &m1[(4 * c + 3) * KP], pk2(w.w));
        }
        float acc[Kk];
        unpk11(a6, acc);
        float b2v = b2[t];
#pragma unroll
        for (int r = 0; r < Kk; r++) {
            float o = hT[t * KP + r] + acc[r] + b2v;
            uT[t * KP + r] = o;
            g_slots[(b * Kk + r) * Dd + t] = o;
            if (last) slots_out[(b * Kk + r) * Dd + t] = o;
        }
    }
    __syncthreads();
    if (last) return;

    // ---- stage 6: pre for next iteration ----
    // LN(slots_new) -> spT (reuse)
    if (wid < Kk) {
        int r = wid;
        float v[6], s = 0.f;
#pragma unroll
        for (int i = 0; i < 6; i++) { v[i] = uT[(lane + 32 * i) * KP + r]; s += v[i]; }
#pragma unroll
        for (int o = 16; o; o >>= 1) s += __shfl_xor_sync(~0u, s, o);
        float mu = s * (1.0f / Dd), q = 0.f;
#pragma unroll
        for (int i = 0; i < 6; i++) { float d = v[i] - mu; q += d * d; }
#pragma unroll
        for (int o = 16; o; o >>= 1) q += __shfl_xor_sync(~0u, q, o);
        float rstd = rsqrtf(q * (1.0f / Dd) + LN_EPSF);
#pragma unroll
        for (int i = 0; i < 6; i++) {
            int d = lane + 32 * i;
            spT[d * KP + r] = (v[i] - mu) * rstd * lnw_s[d] + lnb_s[d];
        }
    }
    __syncthreads();
    // q = sn @ Wq + bq -> P0
    float qa[Kk];
    if (tid < Dd) {
        int t = tid;
        ull a6[6];
#pragma unroll
        for (int j = 0; j < 6; j++) a6[j] = 0ull;
        const float4* w4 = (const float4*)(g_WqT + t * Dd);
#pragma unroll 4
        for (int c = 0; c < 48; c++) {
            float4 w = __ldg(&w4[c]);
            fma12(a6, &spT[(4 * c + 0) * KP], pk2(w.x));
            fma12(a6, &spT[(4 * c + 1) * KP], pk2(w.y));
            fma12(a6, &spT[(4 * c + 2) * KP], pk2(w.z));
            fma12(a6, &spT[(4 * c + 3) * KP], pk2(w.w));
        }
        unpk11(a6, qa);
        float bqv = bq[t];
#pragma unroll
        for (int r = 0; r < Kk; r++) { qa[r] += bqv; P0[t * KP + r] = qa[r]; }
        P0[t * KP + 11] = 0.f;
    }
    __syncthreads();
    // qt = Wk @ q; w2k/cc/sums
    if (tid < Dd) {
        int t = tid;
        ull a6[6];
#pragma unroll
        for (int j = 0; j < 6; j++) a6[j] = 0ull;
        const float4* w4 = (const float4*)(Wk + t * Dd);
#pragma unroll 4
        for (int c = 0; c < 48; c++) {
            float4 w = __ldg(&w4[c]);
            fma12(a6, &P0[(4 * c + 0) * KP], pk2(w.x));
            fma12(a6, &P0[(4 * c + 1) * KP], pk2(w.y));
            fma12(a6, &P0[(4 * c + 2) * KP], pk2(w.z));
            fma12(a6, &P0[(4 * c + 3) * KP], pk2(w.w));
        }
        float qt[Kk];
        unpk11(a6, qt);
        float lwv = lnw_in[t], lbv = lnb_in[t], bkv = bk[t];
        float ws[Kk], cp[Kk];
#pragma unroll
        for (int r = 0; r < Kk; r++) {
            float w2 = qt[r] * SCALEF * lwv;
            g_w2k[(b * Kk + r) * Dd + t] = w2;
            ws[r] = w2;
            cp[r] = (lbv * qt[r] + qa[r] * bkv) * SCALEF;
        }
#pragma unroll
        for (int r = 0; r < Kk; r++) {
            float a = ws[r], c = cp[r];
#pragma unroll
            for (int o = 16; o; o >>= 1) {
                a += __shfl_xor_sync(~0u, a, o);
                c += __shfl_xor_sync(~0u, c, o);
            }
            if (lane == 0) { atomicAdd(&red[r], a); atomicAdd(&red[12 + r], c); }
        }
    }
    __syncthreads();
    if (tid < Kk) {
        g_w2sum[b * Kk + tid] = red[tid];
        g_cc[b * Kk + tid] = red[12 + tid];
        g_s1[b * Kk + tid] = 0.f;
        g_s2[b * Kk + tid] = 0.f;
    }
    for (int i = tid; i < Kk * Dd; i += 576) g_R[b * Kk * Dd + i] = 0.f;
}

extern "C" void kernel_launch(void* const* d_in, const int* in_sizes, int n_in,
                              void* d_out, int out_size) {
    const float* inputs = (const float*)d_in[0];
    const float* noise = (const float*)d_in[1];
    const float* smu = (const float*)d_in[2];
    const float* ssig = (const float*)d_in[3];
    const float* ln_in_w = (const float*)d_in[4];
    const float* ln_in_b = (const float*)d_in[5];
    const float* ln_sl_w = (const float*)d_in[6];
    const float* ln_sl_b = (const float*)d_in[7];
    const float* ln_ml_w = (const float*)d_in[8];
    const float* ln_ml_b = (const float*)d_in[9];
    const float* Wq = (const float*)d_in[10];
    const float* bq = (const float*)d_in[11];
    const float* Wk = (const float*)d_in[12];
    const float* bk = (const float*)d_in[13];
    const float* Wv = (const float*)d_in[14];
    const float* bv = (const float*)d_in[15];
    const float* Wih = (const float*)d_in[16];
    const float* Whh = (const float*)d_in[17];
    const float* bih = (const float*)d_in[18];
    const float* bhh = (const float*)d_in[19];
    const float* W1 = (const float*)d_in[20];
    const float* b1 = (const float*)d_in[21];
    const float* W2 = (const float*)d_in[22];
    const float* b2 = (const float*)d_in[23];

    float* out = (float*)d_out;
    float* slots_out = out;
    float* attn_out = out + Bn * Kk * Dd;

    const int ATTN_SMEM = (Tt * XST + Kk * Dd) * 4;        // 108,800 B
    const int SLOT_SMEM = SLOT_SMEM_FLOATS * 4;            // 107,520 B
    static bool attr_set = false;
    if (!attr_set) {
        cudaFuncSetAttribute(k_attn, cudaFuncAttributeMaxDynamicSharedMemorySize, ATTN_SMEM);
        cudaFuncSetAttribute(k_slot, cudaFuncAttributeMaxDynamicSharedMemorySize, SLOT_SMEM);
        attr_set = true;
    }

    k_init<<<384, 256>>>(noise, smu, ssig, Wq, Wv, W1, W2);
    k_pre<<<Bn, 192>>>(ln_sl_w, ln_sl_b, bq, Wk, bk, ln_in_w, ln_in_b);
    for (int it = 0; it < 3; it++) {
        int last = (it == 2) ? 1 : 0;
        k_attn<<<dim3(Nn / Tt, Bn), 128, ATTN_SMEM>>>(inputs, attn_out, last);
        k_slot<<<Bn, 576, SLOT_SMEM>>>(bv, Wih, Whh, bih, bhh,
                                       ln_in_w, ln_in_b, ln_ml_w, ln_ml_b,
                                       b1, b2, ln_sl_w, ln_sl_b, bq, Wk, bk,
                                       slots_out, last);
    }
}

// round 8
// speedup vs baseline: 1.0155x; 1.0155x over previous
#include <cuda_runtime.h>

#define Bn 64
#define Nn 4096
#define Kk 11
#define KP 12
#define Dd 192
#define HIDn 128
#define Tt 128
#define XST 196
#define EPSF 1e-8f
#define LN_EPSF 1e-5f
#define SCALEF 0.07216878364870323f

typedef unsigned long long ull;

__device__ __forceinline__ ull pk2(float x) {
    ull r; asm("mov.b64 %0, {%1, %1};" : "=l"(r) : "f"(x)); return r;
}
__device__ __forceinline__ ull f2fma(ull a, ull b, ull c) {
    ull d; asm("fma.rn.f32x2 %0, %1, %2, %3;" : "=l"(d) : "l"(a), "l"(b), "l"(c)); return d;
}
__device__ __forceinline__ ull f2add(ull a, ull b) {
    ull d; asm("add.rn.f32x2 %0, %1, %2;" : "=l"(d) : "l"(a), "l"(b)); return d;
}
__device__ __forceinline__ float2 up2(ull v) {
    float lo, hi; asm("mov.b64 {%0, %1}, %2;" : "=f"(lo), "=f"(hi) : "l"(v));
    return make_float2(lo, hi);
}
__device__ __forceinline__ void fma12(ull acc[6], const float* p, ull xx) {
    ulonglong2 q0 = *(const ulonglong2*)p;
    ulonglong2 q1 = *(const ulonglong2*)(p + 4);
    ulonglong2 q2 = *(const ulonglong2*)(p + 8);
    acc[0] = f2fma(q0.x, xx, acc[0]); acc[1] = f2fma(q0.y, xx, acc[1]);
    acc[2] = f2fma(q1.x, xx, acc[2]); acc[3] = f2fma(q1.y, xx, acc[3]);
    acc[4] = f2fma(q2.x, xx, acc[4]); acc[5] = f2fma(q2.y, xx, acc[5]);
}
__device__ __forceinline__ void unpk11(const ull a6[6], float* o) {
#pragma unroll
    for (int j = 0; j < 6; j++) {
        float2 f = up2(a6[j]);
        o[2 * j] = f.x;
        if (2 * j + 1 < Kk) o[2 * j + 1] = f.y;
    }
}

__device__ float g_slots[Bn * Kk * Dd];
__device__ float g_h[Bn * Kk * Dd];
__device__ float g_w2k[Bn * Kk * Dd];
__device__ float g_w2sum[Bn * Kk];
__device__ float g_cc[Bn * Kk];
__device__ float g_R[Bn * Kk * Dd];
__device__ float g_s1[Bn * Kk];
__device__ float g_s2[Bn * Kk];
__device__ float g_WqT[Dd * Dd];
__device__ float g_WvT[Dd * Dd];
__device__ float g_W1T[HIDn * Dd];
__device__ float g_W2T[Dd * HIDn];

// ---------------- init ----------------
__global__ void k_init(const float* __restrict__ noise, const float* __restrict__ smu,
                       const float* __restrict__ ssig, const float* __restrict__ Wq,
                       const float* __restrict__ Wv, const float* __restrict__ W1,
                       const float* __restrict__ W2) {
    const int T0 = Bn * Kk * Dd;
    const int T1 = T0 + Dd * Dd;
    const int T2 = T1 + Dd * Dd;
    const int T3 = T2 + Dd * HIDn;
    const int T4 = T3 + HIDn * Dd;
    for (int i = blockIdx.x * blockDim.x + threadIdx.x; i < T4; i += gridDim.x * blockDim.x) {
        if (i < T0) { int d = i % Dd; g_slots[i] = smu[d] + ssig[d] * noise[i]; }
        else if (i < T1) { int i2 = i - T0; g_WqT[(i2 % Dd) * Dd + i2 / Dd] = Wq[i2]; }
        else if (i < T2) { int i2 = i - T1; g_WvT[(i2 % Dd) * Dd + i2 / Dd] = Wv[i2]; }
        else if (i < T3) { int i2 = i - T2; g_W1T[(i2 % HIDn) * Dd + i2 / HIDn] = W1[i2]; }
        else { int i2 = i - T3; g_W2T[(i2 % Dd) * HIDn + i2 / Dd] = W2[i2]; }
    }
}

// ---------------- per-iter slot preprocessing ----------------
__global__ __launch_bounds__(192) void k_pre(const float* __restrict__ lnw_s,
                                             const float* __restrict__ lnb_s,
                                             const float* __restrict__ bq,
                                             const float* __restrict__ Wk,
                                             const float* __restrict__ bk,
                                             const float* __restrict__ lnw_in,
                                             const float* __restrict__ lnb_in) {
    __shared__ float snt[Dd * KP];
    __shared__ float qT[Dd * KP];
    __shared__ float red[24];
    int b = blockIdx.x, t = threadIdx.x, wid = t >> 5, lane = t & 31;
    if (t < 24) red[t] = 0.f;
    snt[t * KP + 11] = 0.f;

    for (int r = wid; r < Kk; r += 6) {
        float v[6], s = 0.f;
#pragma unroll
        for (int i = 0; i < 6; i++) { v[i] = g_slots[(b * Kk + r) * Dd + lane + 32 * i]; s += v[i]; }
#pragma unroll
        for (int o = 16; o; o >>= 1) s += __shfl_xor_sync(~0u, s, o);
        float mu = s * (1.0f / Dd), q = 0.f;
#pragma unroll
        for (int i = 0; i < 6; i++) { float d = v[i] - mu; q += d * d; }
#pragma unroll
        for (int o = 16; o; o >>= 1) q += __shfl_xor_sync(~0u, q, o);
        float rstd = rsqrtf(q * (1.0f / Dd) + LN_EPSF);
#pragma unroll
        for (int i = 0; i < 6; i++) {
            int d = lane + 32 * i;
            snt[d * KP + r] = (v[i] - mu) * rstd * lnw_s[d] + lnb_s[d];
        }
    }
    __syncthreads();

    ull a6[6];
#pragma unroll
    for (int j = 0; j < 6; j++) a6[j] = 0ull;
    {
        const float4* w4 = (const float4*)(g_WqT + t * Dd);
#pragma unroll 4
        for (int c = 0; c < 48; c++) {
            float4 w = __ldg(&w4[c]);
            fma12(a6, &snt[(4 * c + 0) * KP], pk2(w.x));
            fma12(a6, &snt[(4 * c + 1) * KP], pk2(w.y));
            fma12(a6, &snt[(4 * c + 2) * KP], pk2(w.z));
            fma12(a6, &snt[(4 * c + 3) * KP], pk2(w.w));
        }
    }
    float qa[Kk];
    unpk11(a6, qa);
    float bqv = bq[t];
#pragma unroll
    for (int r = 0; r < Kk; r++) { qa[r] += bqv; qT[t * KP + r] = qa[r]; }
    qT[t * KP + 11] = 0.f;
    __syncthreads();

#pragma unroll
    for (int j = 0; j < 6; j++) a6[j] = 0ull;
    {
        const float4* w4 = (const float4*)(Wk + t * Dd);
#pragma unroll 4
        for (int c = 0; c < 48; c++) {
            float4 w = __ldg(&w4[c]);
            fma12(a6, &qT[(4 * c + 0) * KP], pk2(w.x));
            fma12(a6, &qT[(4 * c + 1) * KP], pk2(w.y));
            fma12(a6, &qT[(4 * c + 2) * KP], pk2(w.z));
            fma12(a6, &qT[(4 * c + 3) * KP], pk2(w.w));
        }
    }
    float qt[Kk];
    unpk11(a6, qt);
    float lwv = lnw_in[t], lbv = lnb_in[t], bkv = bk[t];
    float ws[Kk], cp[Kk];
#pragma unroll
    for (int r = 0; r < Kk; r++) {
        float w2 = qt[r] * SCALEF * lwv;
        g_w2k[(b * Kk + r) * Dd + t] = w2;
        ws[r] = w2;
        cp[r] = (lbv * qt[r] + qa[r] * bkv) * SCALEF;
    }
#pragma unroll
    for (int r = 0; r < Kk; r++) {
        float a = ws[r], c = cp[r];
#pragma unroll
        for (int o = 16; o; o >>= 1) {
            a += __shfl_xor_sync(~0u, a, o);
            c += __shfl_xor_sync(~0u, c, o);
        }
        if (lane == 0) { atomicAdd(&red[r], a); atomicAdd(&red[12 + r], c); }
    }
    __syncthreads();
    if (t < Kk) {
        g_w2sum[b * Kk + t] = red[t];
        g_cc[b * Kk + t] = red[12 + t];
        g_s1[b * Kk + t] = 0.f;
        g_s2[b * Kk + t] = 0.f;
    }
    for (int i = t; i < Kk * Dd; i += 192) g_R[b * Kk * Dd + i] = 0.f;
}

// ---------------- attention pass: 64 threads, 2 tokens/thread ----------------
__global__ __launch_bounds__(64) void k_attn(const float* __restrict__ x,
                                             float* __restrict__ attn_out, int wr) {
    extern __shared__ float sm[];
    float* Xs = sm;                 // Tt rows, stride XST
    float* Ws = sm + Tt * XST;      // [k][192] (phase B); aliased by A1 in phase C
    float* A1 = Ws;                 // Tt x KP
    int b = blockIdx.y, tid = threadIdx.x, lane = tid & 31;
    int n0 = blockIdx.x * Tt;

    // phase A: load raw x tile + w2 rows
    const float* xb = x + ((size_t)(b * Nn + n0)) * Dd;
#pragma unroll 4
    for (int i = tid * 4; i < Tt * Dd; i += 64 * 4) {
        float4 v = __ldcs((const float4*)(xb + i));
        int t = i / Dd, d = i - t * Dd;
        *(float4*)&Xs[t * XST + d] = v;
    }
    const float* wsrc = g_w2k + b * Kk * Dd;
    for (int i = tid; i < Kk * Dd; i += 64) Ws[i] = wsrc[i];
    __syncthreads();

    // phase B: two tokens per thread share every Ws load
    ull aA0[Kk], aB0[Kk], aA1[Kk], aB1[Kk];
#pragma unroll
    for (int k = 0; k < Kk; k++) { aA0[k] = 0ull; aB0[k] = 0ull; aA1[k] = 0ull; aB1[k] = 0ull; }
    ull sS0 = 0ull, sQ0 = 0ull, sS1 = 0ull, sQ1 = 0ull;
    const ulonglong2* xr0 = (const ulonglong2*)(Xs + tid * XST);
    const ulonglong2* xr1 = (const ulonglong2*)(Xs + (tid + 64) * XST);
#pragma unroll 2
    for (int c = 0; c < 48; c++) {
        ulonglong2 x0 = xr0[c];
        ulonglong2 x1 = xr1[c];
        sS0 = f2add(sS0, f2add(x0.x, x0.y));
        sQ0 = f2fma(x0.x, x0.x, sQ0); sQ0 = f2fma(x0.y, x0.y, sQ0);
        sS1 = f2add(sS1, f2add(x1.x, x1.y));
        sQ1 = f2fma(x1.x, x1.x, sQ1); sQ1 = f2fma(x1.y, x1.y, sQ1);
#pragma unroll
        for (int k = 0; k < Kk; k++) {
            ulonglong2 wv = *(const ulonglong2*)&Ws[k * Dd + c * 4];
            aA0[k] = f2fma(x0.x, wv.x, aA0[k]);
            aB0[k] = f2fma(x0.y, wv.y, aB0[k]);
            aA1[k] = f2fma(x1.x, wv.x, aA1[k]);
            aB1[k] = f2fma(x1.y, wv.y, aB1[k]);
        }
    }
    float w2s[Kk], ccv[Kk];
#pragma unroll
    for (int k = 0; k < Kk; k++) {
        w2s[k] = __ldg(&g_w2sum[b * Kk + k]);
        ccv[k] = __ldg(&g_cc[b * Kk + k]);
    }
    // token 0 stats/softmax
    float2 sf0 = up2(sS0), qf0 = up2(sQ0);
    float mu0 = (sf0.x + sf0.y) * (1.0f / Dd);
    float rs0 = rsqrtf((qf0.x + qf0.y) * (1.0f / Dd) - mu0 * mu0 + LN_EPSF);
    float rm0 = rs0 * mu0;
    float2 sf1 = up2(sS1), qf1 = up2(sQ1);
    float mu1 = (sf1.x + sf1.y) * (1.0f / Dd);
    float rs1 = rsqrtf((qf1.x + qf1.y) * (1.0f / Dd) - mu1 * mu1 + LN_EPSF);
    float rm1 = rs1 * mu1;

    float dk0[Kk], dk1[Kk];
#pragma unroll
    for (int k = 0; k < Kk; k++) {
        float2 fa = up2(aA0[k]), fb = up2(aB0[k]);
        dk0[k] = rs0 * ((fa.x + fa.y) + (fb.x + fb.y)) - rm0 * w2s[k] + ccv[k];
        float2 ga = up2(aA1[k]), gb = up2(aB1[k]);
        dk1[k] = rs1 * ((ga.x + ga.y) + (gb.x + gb.y)) - rm1 * w2s[k] + ccv[k];
    }
    float mx0 = dk0[0], mx1 = dk1[0];
#pragma unroll
    for (int k = 1; k < Kk; k++) { mx0 = fmaxf(mx0, dk0[k]); mx1 = fmaxf(mx1, dk1[k]); }
    float sum0 = 0.f, sum1 = 0.f;
#pragma unroll
    for (int k = 0; k < Kk; k++) {
        dk0[k] = __expf(dk0[k] - mx0); sum0 += dk0[k];
        dk1[k] = __expf(dk1[k] - mx1); sum1 += dk1[k];
    }
    float inv0 = __fdividef(1.0f, sum0), inv1 = __fdividef(1.0f, sum1);
#pragma unroll
    for (int k = 0; k < Kk; k++) {
        dk0[k] = fmaf(dk0[k], inv0, EPSF);
        dk1[k] = fmaf(dk1[k], inv1, EPSF);
    }
    if (wr) {
        int n = n0 + tid;
#pragma unroll
        for (int k = 0; k < Kk; k++) {
            attn_out[((size_t)(b * Kk + k)) * Nn + n] = dk0[k];
            attn_out[((size_t)(b * Kk + k)) * Nn + n + 64] = dk1[k];
        }
    }
    // s1/s2 reductions (both tokens combined before shuffle)
#pragma unroll
    for (int k = 0; k < Kk; k++) {
        float s1v = dk0[k] + dk1[k];
        float s2v = dk0[k] * rm0 + dk1[k] * rm1;
#pragma unroll
        for (int o = 16; o; o >>= 1) {
            s1v += __shfl_xor_sync(~0u, s1v, o);
            s2v += __shfl_xor_sync(~0u, s2v, o);
        }
        if (lane == 0) {
            atomicAdd(&g_s1[b * Kk + k], s1v);
            atomicAdd(&g_s2[b * Kk + k], s2v);
        }
    }
    __syncthreads();  // all Ws reads done
#pragma unroll
    for (int k = 0; k < Kk; k++) {
        A1[tid * KP + k] = dk0[k] * rs0;
        A1[(tid + 64) * KP + k] = dk1[k] * rs1;
    }
    A1[tid * KP + 11] = 0.f;
    A1[(tid + 64) * KP + 11] = 0.f;
    __syncthreads();

    // phase C: 3 d's per thread, A1 loads shared
    {
        int d0 = tid, d1 = tid + 64, d2 = tid + 128;
        ull c0[6], c1[6], c2[6];
#pragma unroll
        for (int j = 0; j < 6; j++) { c0[j] = 0ull; c1[j] = 0ull; c2[j] = 0ull; }
#pragma unroll 2
        for (int t = 0; t < Tt; t++) {
            const float* a1p = &A1[t * KP];
            ulonglong2 q0 = *(const ulonglong2*)a1p;
            ulonglong2 q1 = *(const ulonglong2*)(a1p + 4);
            ulonglong2 q2 = *(const ulonglong2*)(a1p + 8);
            const float* xrow = &Xs[t * XST];
            ull xx0 = pk2(xrow[d0]);
            ull xx1 = pk2(xrow[d1]);
            ull xx2 = pk2(xrow[d2]);
            c0[0] = f2fma(q0.x, xx0, c0[0]); c0[1] = f2fma(q0.y, xx0, c0[1]);
            c0[2] = f2fma(q1.x, xx0, c0[2]); c0[3] = f2fma(q1.y, xx0, c0[3]);
            c0[4] = f2fma(q2.x, xx0, c0[4]); c0[5] = f2fma(q2.y, xx0, c0[5]);
            c1[0] = f2fma(q0.x, xx1, c1[0]); c1[1] = f2fma(q0.y, xx1, c1[1]);
            c1[2] = f2fma(q1.x, xx1, c1[2]); c1[3] = f2fma(q1.y, xx1, c1[3]);
            c1[4] = f2fma(q2.x, xx1, c1[4]); c1[5] = f2fma(q2.y, xx1, c1[5]);
            c2[0] = f2fma(q0.x, xx2, c2[0]); c2[1] = f2fma(q0.y, xx2, c2[1]);
            c2[2] = f2fma(q1.x, xx2, c2[2]); c2[3] = f2fma(q1.y, xx2, c2[3]);
            c2[4] = f2fma(q2.x, xx2, c2[4]); c2[5] = f2fma(q2.y, xx2, c2[5]);
        }
        float* Rb = g_R + b * Kk * Dd;
#pragma unroll
        for (int j = 0; j < 6; j++) {
            float2 f0 = up2(c0[j]), f1 = up2(c1[j]), f2v = up2(c2[j]);
            atomicAdd(&Rb[(2 * j) * Dd + d0], f0.x);
            atomicAdd(&Rb[(2 * j) * Dd + d1], f1.x);
            atomicAdd(&Rb[(2 * j) * Dd + d2], f2v.x);
            if (2 * j + 1 < Kk) {
                atomicAdd(&Rb[(2 * j + 1) * Dd + d0], f0.y);
                atomicAdd(&Rb[(2 * j + 1) * Dd + d1], f1.y);
                atomicAdd(&Rb[(2 * j + 1) * Dd + d2], f2v.y);
            }
        }
    }
}

// ---------------- GRU ----------------
__global__ __launch_bounds__(288) void k_gru(const float* __restrict__ bv,
                                             const float* __restrict__ Wih,
                                             const float* __restrict__ Whh,
                                             const float* __restrict__ bih,
                                             const float* __restrict__ bhh,
                                             const float* __restrict__ lnw_in,
                                             const float* __restrict__ lnb_in) {
    __shared__ float uT[Dd * KP], spT[Dd * KP], vT[Dd * KP];
    __shared__ float P0[96 * KP], P1[96 * KP], PXn[96 * KP], PHn[96 * KP];
    __shared__ float sinv[Kk], s2s[Kk];
    int hh = blockIdx.x, b = blockIdx.y, tid = threadIdx.x;
    if (tid < Kk) {
        sinv[tid] = __fdividef(1.0f, g_s1[b * Kk + tid]);
        s2s[tid] = g_s2[b * Kk + tid];
    }
    __syncthreads();
    for (int i = tid; i < Dd; i += 288) { uT[i * KP + 11] = 0.f; spT[i * KP + 11] = 0.f; }
    for (int i = tid; i < Kk * Dd; i += 288) {
        int r = i / Dd, d = i - r * Dd;
        float R = g_R[b * Kk * Dd + i];
        uT[d * KP + r] = lnw_in[d] * (R - s2s[r]) * sinv[r] + lnb_in[d];
        spT[d * KP + r] = g_slots[b * Kk * Dd + i];
    }
    __syncthreads();
    if (tid < Dd) {
        ull a6[6];
#pragma unroll
        for (int j = 0; j < 6; j++) a6[j] = 0ull;
        const float4* w4 = (const float4*)(g_WvT + tid * Dd);
#pragma unroll 4
        for (int c = 0; c < 48; c++) {
            float4 w = __ldg(&w4[c]);
            fma12(a6, &uT[(4 * c + 0) * KP], pk2(w.x));
            fma12(a6, &uT[(4 * c + 1) * KP], pk2(w.y));
            fma12(a6, &uT[(4 * c + 2) * KP], pk2(w.z));
            fma12(a6, &uT[(4 * c + 3) * KP], pk2(w.w));
        }
        float vv[Kk];
        unpk11(a6, vv);
        float bvv = bv[tid];
#pragma unroll
        for (int r = 0; r < Kk; r++) vT[tid * KP + r] = vv[r] + bvv;
        vT[tid * KP + 11] = 0.f;
    }
    __syncthreads();
    int g = tid / 96, tl = tid - g * 96, t = hh * 96 + tl;
    int j = g * Dd + t;
    ull ax6[6], ah6[6];
#pragma unroll
    for (int jj = 0; jj < 6; jj++) { ax6[jj] = 0ull; ah6[jj] = 0ull; }
    const float4* wi4 = (const float4*)(Wih + j * Dd);
    const float4* wh4 = (const float4*)(Whh + j * Dd);
#pragma unroll 4
    for (int c = 0; c < 48; c++) {
        float4 wi = __ldg(&wi4[c]);
        float4 wh = __ldg(&wh4[c]);
        fma12(ax6, &vT[(4 * c + 0) * KP], pk2(wi.x));
        fma12(ax6, &vT[(4 * c + 1) * KP], pk2(wi.y));
        fma12(ax6, &vT[(4 * c + 2) * KP], pk2(wi.z));
        fma12(ax6, &vT[(4 * c + 3) * KP], pk2(wi.w));
        fma12(ah6, &spT[(4 * c + 0) * KP], pk2(wh.x));
        fma12(ah6, &spT[(4 * c + 1) * KP], pk2(wh.y));
        fma12(ah6, &spT[(4 * c + 2) * KP], pk2(wh.z));
        fma12(ah6, &spT[(4 * c + 3) * KP], pk2(wh.w));
    }
    float axf[Kk], ahf[Kk];
    unpk11(ax6, axf); unpk11(ah6, ahf);
    float bi = bih[j], bh = bhh[j];
    if (g == 0) {
#pragma unroll
        for (int r = 0; r < Kk; r++) P0[tl * KP + r] = axf[r] + ahf[r] + bi + bh;
    } else if (g == 1) {
#pragma unroll
        for (int r = 0; r < Kk; r++) P1[tl * KP + r] = axf[r] + ahf[r] + bi + bh;
    } else {
#pragma unroll
        for (int r = 0; r < Kk; r++) { PXn[tl * KP + r] = axf[r] + bi; PHn[tl * KP + r] = ahf[r] + bh; }
    }
    __syncthreads();
    for (int i = tid; i < Kk * 96; i += 288) {
        int r = i / 96, tl2 = i - r * 96, tg = hh * 96 + tl2;
        float rg = 1.0f / (1.0f + __expf(-P0[tl2 * KP + r]));
        float zg = 1.0f / (1.0f + __expf(-P1[tl2 * KP + r]));
        float ng = tanhf(fmaf(rg, PHn[tl2 * KP + r], PXn[tl2 * KP + r]));
        float hp = spT[tg * KP + r];
        g_h[(b * Kk + r) * Dd + tg] = (1.0f - zg) * ng + zg * hp;
    }
}

// ---------------- LN + MLP + residual ----------------
__global__ __launch_bounds__(192) void k_mlp(const float* __restrict__ lnw,
                                             const float* __restrict__ lnb,
                                             const float* __restrict__ b1,
                                             const float* __restrict__ b2,
                                             float* __restrict__ slots_out, int last) {
    __shared__ float hT[Dd * KP];
    __shared__ float m1T[HIDn * KP];
    int b = blockIdx.x, t = threadIdx.x, wid = t >> 5, lane = t & 31;
    hT[t * KP + 11] = 0.f;
    if (t < HIDn) m1T[t * KP + 11] = 0.f;
    for (int r = wid; r < Kk; r += 6) {
        float v[6], s = 0.f;
#pragma unroll
        for (int i = 0; i < 6; i++) { v[i] = g_h[(b * Kk + r) * Dd + lane + 32 * i]; s += v[i]; }
#pragma unroll
        for (int o = 16; o; o >>= 1) s += __shfl_xor_sync(~0u, s, o);
        float mu = s * (1.0f / Dd), q = 0.f;
#pragma unroll
        for (int i = 0; i < 6; i++) { float d = v[i] - mu; q += d * d; }
#pragma unroll
        for (int o = 16; o; o >>= 1) q += __shfl_xor_sync(~0u, q, o);
        float rstd = rsqrtf(q * (1.0f / Dd) + LN_EPSF);
#pragma unroll
        for (int i = 0; i < 6; i++) {
            int d = lane + 32 * i;
            hT[d * KP + r] = (v[i] - mu) * rstd * lnw[d] + lnb[d];
        }
    }
    __syncthreads();
    if (t < HIDn) {
        ull a6[6];
#pragma unroll
        for (int j = 0; j < 6; j++) a6[j] = 0ull;
        const float4* w4 = (const float4*)(g_W1T + t * Dd);
#pragma unroll 4
        for (int c = 0; c < 48; c++) {
            float4 w = __ldg(&w4[c]);
            fma12(a6, &hT[(4 * c + 0) * KP], pk2(w.x));
            fma12(a6, &hT[(4 * c + 1) * KP], pk2(w.y));
            fma12(a6, &hT[(4 * c + 2) * KP], pk2(w.z));
            fma12(a6, &hT[(4 * c + 3) * KP], pk2(w.w));
        }
        float vv[Kk];
        unpk11(a6, vv);
        float b1v = b1[t];
#pragma unroll
        for (int r = 0; r < Kk; r++) m1T[t * KP + r] = fmaxf(vv[r] + b1v, 0.0f);
    }
    __syncthreads();
    ull a6[6];
#pragma unroll
    for (int j = 0; j < 6; j++) a6[j] = 0ull;
    {
        const float4* w4 = (const float4*)(g_W2T + t * HIDn);
#pragma unroll 4
        for (int c = 0; c < 32; c++) {
            float4 w = __ldg(&w4[c]);
            fma12(a6, &m1T[(4 * c + 0) * KP], pk2(w.x));
            fma12(a6, &m1T[(4 * c + 1) * KP], pk2(w.y));
            fma12(a6, &m1T[(4 * c + 2) * KP], pk2(w.z));
            fma12(a6, &m1T[(4 * c + 3) * KP], pk2(w.w));
        }
    }
    float acc[Kk];
    unpk11(a6, acc);
    float b2v = b2[t];
#pragma unroll
    for (int r = 0; r < Kk; r++) {
        float o = g_h[(b * Kk + r) * Dd + t] + acc[r] + b2v;
        g_slots[(b * Kk + r) * Dd + t] = o;
        if (last) slots_out[(b * Kk + r) * Dd + t] = o;
    }
}

extern "C" void kernel_launch(void* const* d_in, const int* in_sizes, int n_in,
                              void* d_out, int out_size) {
    const float* inputs = (const float*)d_in[0];
    const float* noise = (const float*)d_in[1];
    const float* smu = (const float*)d_in[2];
    const float* ssig = (const float*)d_in[3];
    const float* ln_in_w = (const float*)d_in[4];
    const float* ln_in_b = (const float*)d_in[5];
    const float* ln_sl_w = (const float*)d_in[6];
    const float* ln_sl_b = (const float*)d_in[7];
    const float* ln_ml_w = (const float*)d_in[8];
    const float* ln_ml_b = (const float*)d_in[9];
    const float* Wq = (const float*)d_in[10];
    const float* bq = (const float*)d_in[11];
    const float* Wk = (const float*)d_in[12];
    const float* bk = (const float*)d_in[13];
    const float* Wv = (const float*)d_in[14];
    const float* bv = (const float*)d_in[15];
    const float* Wih = (const float*)d_in[16];
    const float* Whh = (const float*)d_in[17];
    const float* bih = (const float*)d_in[18];
    const float* bhh = (const float*)d_in[19];
    const float* W1 = (const float*)d_in[20];
    const float* b1 = (const float*)d_in[21];
    const float* W2 = (const float*)d_in[22];
    const float* b2 = (const float*)d_in[23];

    float* out = (float*)d_out;
    float* slots_out = out;
    float* attn_out = out + Bn * Kk * Dd;

    const int ATTN_SMEM = (Tt * XST + Kk * Dd) * 4;  // 108,800 bytes
    static bool attr_set = false;
    if (!attr_set) {
        cudaFuncSetAttribute(k_attn, cudaFuncAttributeMaxDynamicSharedMemorySize, ATTN_SMEM);
        attr_set = true;
    }

    k_init<<<384, 256>>>(noise, smu, ssig, Wq, Wv, W1, W2);
    for (int it = 0; it < 3; it++) {
        int last = (it == 2) ? 1 : 0;
        k_pre<<<Bn, 192>>>(ln_sl_w, ln_sl_b, bq, Wk, bk, ln_in_w, ln_in_b);
        k_attn<<<dim3(Nn / Tt, Bn), 64, ATTN_SMEM>>>(inputs, attn_out, last);
        k_gru<<<dim3(2, Bn), 288>>>(bv, Wih, Whh, bih, bhh, ln_in_w, ln_in_b);
        k_mlp<<<Bn, 192>>>(ln_ml_w, ln_ml_b, b1, b2, slots_out, last);
    }
}

// round 9
// speedup vs baseline: 1.1881x; 1.1700x over previous
#include <cuda_runtime.h>

#define Bn 64
#define Nn 4096
#define Kk 11
#define KP 12
#define Dd 192
#define HIDn 128
#define Tt 128
#define XST 196
#define EPSF 1e-8f
#define LN_EPSF 1e-5f
#define SCALEF 0.07216878364870323f

typedef unsigned long long ull;

__device__ __forceinline__ ull pk2(float x) {
    ull r; asm("mov.b64 %0, {%1, %1};" : "=l"(r) : "f"(x)); return r;
}
__device__ __forceinline__ ull f2fma(ull a, ull b, ull c) {
    ull d; asm("fma.rn.f32x2 %0, %1, %2, %3;" : "=l"(d) : "l"(a), "l"(b), "l"(c)); return d;
}
__device__ __forceinline__ ull f2add(ull a, ull b) {
    ull d; asm("add.rn.f32x2 %0, %1, %2;" : "=l"(d) : "l"(a), "l"(b)); return d;
}
__device__ __forceinline__ float2 up2(ull v) {
    float lo, hi; asm("mov.b64 {%0, %1}, %2;" : "=f"(lo), "=f"(hi) : "l"(v));
    return make_float2(lo, hi);
}
__device__ __forceinline__ void fma12(ull acc[6], const float* p, ull xx) {
    ulonglong2 q0 = *(const ulonglong2*)p;
    ulonglong2 q1 = *(const ulonglong2*)(p + 4);
    ulonglong2 q2 = *(const ulonglong2*)(p + 8);
    acc[0] = f2fma(q0.x, xx, acc[0]); acc[1] = f2fma(q0.y, xx, acc[1]);
    acc[2] = f2fma(q1.x, xx, acc[2]); acc[3] = f2fma(q1.y, xx, acc[3]);
    acc[4] = f2fma(q2.x, xx, acc[4]); acc[5] = f2fma(q2.y, xx, acc[5]);
}
__device__ __forceinline__ void unpk11(const ull a6[6], float* o) {
#pragma unroll
    for (int j = 0; j < 6; j++) {
        float2 f = up2(a6[j]);
        o[2 * j] = f.x;
        if (2 * j + 1 < Kk) o[2 * j + 1] = f.y;
    }
}

__device__ float g_slots[Bn * Kk * Dd];
__device__ float g_h[Bn * Kk * Dd];
__device__ float g_w2k[Bn * Kk * Dd];
__device__ float g_w2sum[Bn * Kk];
__device__ float g_cc[Bn * Kk];
__device__ float g_R[Bn * Kk * Dd];
__device__ float g_s1[Bn * Kk];
__device__ float g_s2[Bn * Kk];
__device__ float g_WqT[Dd * Dd];
__device__ float g_WvT[Dd * Dd];
__device__ float g_W1T[HIDn * Dd];
__device__ float g_W2T[Dd * HIDn];

// ---------------- init ----------------
__global__ void k_init(const float* __restrict__ noise, const float* __restrict__ smu,
                       const float* __restrict__ ssig, const float* __restrict__ Wq,
                       const float* __restrict__ Wv, const float* __restrict__ W1,
                       const float* __restrict__ W2) {
    const int T0 = Bn * Kk * Dd;
    const int T1 = T0 + Dd * Dd;
    const int T2 = T1 + Dd * Dd;
    const int T3 = T2 + Dd * HIDn;
    const int T4 = T3 + HIDn * Dd;
    for (int i = blockIdx.x * blockDim.x + threadIdx.x; i < T4; i += gridDim.x * blockDim.x) {
        if (i < T0) { int d = i % Dd; g_slots[i] = smu[d] + ssig[d] * noise[i]; }
        else if (i < T1) { int i2 = i - T0; g_WqT[(i2 % Dd) * Dd + i2 / Dd] = Wq[i2]; }
        else if (i < T2) { int i2 = i - T1; g_WvT[(i2 % Dd) * Dd + i2 / Dd] = Wv[i2]; }
        else if (i < T3) { int i2 = i - T2; g_W1T[(i2 % HIDn) * Dd + i2 / HIDn] = W1[i2]; }
        else { int i2 = i - T3; g_W2T[(i2 % Dd) * HIDn + i2 / Dd] = W2[i2]; }
    }
}

// ---------------- per-iter slot preprocessing ----------------
__global__ __launch_bounds__(192) void k_pre(const float* __restrict__ lnw_s,
                                             const float* __restrict__ lnb_s,
                                             const float* __restrict__ bq,
                                             const float* __restrict__ Wk,
                                             const float* __restrict__ bk,
                                             const float* __restrict__ lnw_in,
                                             const float* __restrict__ lnb_in) {
    __shared__ float snt[Dd * KP];
    __shared__ float qT[Dd * KP];
    __shared__ float red[24];
    int b = blockIdx.x, t = threadIdx.x, wid = t >> 5, lane = t & 31;
    if (t < 24) red[t] = 0.f;
    snt[t * KP + 11] = 0.f;

    for (int r = wid; r < Kk; r += 6) {
        float v[6], s = 0.f;
#pragma unroll
        for (int i = 0; i < 6; i++) { v[i] = g_slots[(b * Kk + r) * Dd + lane + 32 * i]; s += v[i]; }
#pragma unroll
        for (int o = 16; o; o >>= 1) s += __shfl_xor_sync(~0u, s, o);
        float mu = s * (1.0f / Dd), q = 0.f;
#pragma unroll
        for (int i = 0; i < 6; i++) { float d = v[i] - mu; q += d * d; }
#pragma unroll
        for (int o = 16; o; o >>= 1) q += __shfl_xor_sync(~0u, q, o);
        float rstd = rsqrtf(q * (1.0f / Dd) + LN_EPSF);
#pragma unroll
        for (int i = 0; i < 6; i++) {
            int d = lane + 32 * i;
            snt[d * KP + r] = (v[i] - mu) * rstd * lnw_s[d] + lnb_s[d];
        }
    }
    __syncthreads();

    ull a6[6];
#pragma unroll
    for (int j = 0; j < 6; j++) a6[j] = 0ull;
    {
        const float4* w4 = (const float4*)(g_WqT + t * Dd);
#pragma unroll 4
        for (int c = 0; c < 48; c++) {
            float4 w = __ldg(&w4[c]);
            fma12(a6, &snt[(4 * c + 0) * KP], pk2(w.x));
            fma12(a6, &snt[(4 * c + 1) * KP], pk2(w.y));
            fma12(a6, &snt[(4 * c + 2) * KP], pk2(w.z));
            fma12(a6, &snt[(4 * c + 3) * KP], pk2(w.w));
        }
    }
    float qa[Kk];
    unpk11(a6, qa);
    float bqv = bq[t];
#pragma unroll
    for (int r = 0; r < Kk; r++) { qa[r] += bqv; qT[t * KP + r] = qa[r]; }
    qT[t * KP + 11] = 0.f;
    __syncthreads();

#pragma unroll
    for (int j = 0; j < 6; j++) a6[j] = 0ull;
    {
        const float4* w4 = (const float4*)(Wk + t * Dd);
#pragma unroll 4
        for (int c = 0; c < 48; c++) {
            float4 w = __ldg(&w4[c]);
            fma12(a6, &qT[(4 * c + 0) * KP], pk2(w.x));
            fma12(a6, &qT[(4 * c + 1) * KP], pk2(w.y));
            fma12(a6, &qT[(4 * c + 2) * KP], pk2(w.z));
            fma12(a6, &qT[(4 * c + 3) * KP], pk2(w.w));
        }
    }
    float qt[Kk];
    unpk11(a6, qt);
    float lwv = lnw_in[t], lbv = lnb_in[t], bkv = bk[t];
    float ws[Kk], cp[Kk];
#pragma unroll
    for (int r = 0; r < Kk; r++) {
        float w2 = qt[r] * SCALEF * lwv;
        g_w2k[(b * Kk + r) * Dd + t] = w2;
        ws[r] = w2;
        cp[r] = (lbv * qt[r] + qa[r] * bkv) * SCALEF;
    }
#pragma unroll
    for (int r = 0; r < Kk; r++) {
        float a = ws[r], c = cp[r];
#pragma unroll
        for (int o = 16; o; o >>= 1) {
            a += __shfl_xor_sync(~0u, a, o);
            c += __shfl_xor_sync(~0u, c, o);
        }
        if (lane == 0) { atomicAdd(&red[r], a); atomicAdd(&red[12 + r], c); }
    }
    __syncthreads();
    if (t < Kk) {
        g_w2sum[b * Kk + t] = red[t];
        g_cc[b * Kk + t] = red[12 + t];
        g_s1[b * Kk + t] = 0.f;
        g_s2[b * Kk + t] = 0.f;
    }
    for (int i = t; i < Kk * Dd; i += 192) g_R[b * Kk * Dd + i] = 0.f;
}

// ---------------- attention pass: 256 threads, 2 threads/token (in-warp halves) ----
__global__ __launch_bounds__(256, 2) void k_attn(const float* __restrict__ x,
                                                 float* __restrict__ attn_out, int wr) {
    extern __shared__ float sm[];
    float* Xs = sm;                 // Tt rows, stride XST
    float* Ws = sm + Tt * XST;      // [k][192] (phase B); aliased by A1 in phase C
    float* A1 = Ws;                 // Tt x KP
    int b = blockIdx.y, tid = threadIdx.x;
    int lane = tid & 31, warp = tid >> 5;
    int half = lane >> 4;                 // 0/1: which 96-d half of the row
    int t = warp * 16 + (lane & 15);      // token 0..127
    int n0 = blockIdx.x * Tt;

    // phase A: load raw x tile + w2 rows
    const float* xb = x + ((size_t)(b * Nn + n0)) * Dd;
    for (int i = tid * 4; i < Tt * Dd; i += 256 * 4) {
        float4 v = __ldcs((const float4*)(xb + i));
        int tt = i / Dd, d = i - tt * Dd;
        *(float4*)&Xs[tt * XST + d] = v;
    }
    const float* wsrc = g_w2k + b * Kk * Dd;
    for (int i = tid; i < Kk * Dd; i += 256) Ws[i] = wsrc[i];
    __syncthreads();

    // phase B: partial stats + dots over this thread's 96 d's
    ull aA[Kk], aB[Kk];
#pragma unroll
    for (int k = 0; k < Kk; k++) { aA[k] = 0ull; aB[k] = 0ull; }
    ull sS = 0ull, sQ = 0ull;
    const int cbase = half * 96;   // float offset of this half
    const ulonglong2* xr2 = (const ulonglong2*)(Xs + t * XST + cbase);
#pragma unroll 2
    for (int c = 0; c < 24; c++) {
        ulonglong2 xv = xr2[c];
        sS = f2add(sS, f2add(xv.x, xv.y));
        sQ = f2fma(xv.x, xv.x, sQ); sQ = f2fma(xv.y, xv.y, sQ);
        const float* wrow = &Ws[cbase + c * 4];
#pragma unroll
        for (int k = 0; k < Kk; k++) {
            ulonglong2 wv = *(const ulonglong2*)&wrow[k * Dd];
            aA[k] = f2fma(xv.x, wv.x, aA[k]);
            aB[k] = f2fma(xv.y, wv.y, aB[k]);
        }
    }
    float dots[Kk];
#pragma unroll
    for (int k = 0; k < Kk; k++) {
        float2 fa = up2(aA[k]), fb = up2(aB[k]);
        dots[k] = (fa.x + fa.y) + (fb.x + fb.y);
    }
    float2 sf = up2(sS), qf = up2(sQ);
    float sSf = sf.x + sf.y, sQf = qf.x + qf.y;
    // cross-half combine within the warp (partner lane = lane ^ 16)
    sSf += __shfl_xor_sync(~0u, sSf, 16);
    sQf += __shfl_xor_sync(~0u, sQf, 16);
#pragma unroll
    for (int k = 0; k < Kk; k++) dots[k] += __shfl_xor_sync(~0u, dots[k], 16);

    float mu = sSf * (1.0f / Dd);
    float rs = rsqrtf(sQf * (1.0f / Dd) - mu * mu + LN_EPSF);
    float rm = rs * mu;
    float dk[Kk];
#pragma unroll
    for (int k = 0; k < Kk; k++)
        dk[k] = rs * dots[k] - rm * __ldg(&g_w2sum[b * Kk + k]) + __ldg(&g_cc[b * Kk + k]);
    float mx = dk[0];
#pragma unroll
    for (int k = 1; k < Kk; k++) mx = fmaxf(mx, dk[k]);
    float sum = 0.f;
#pragma unroll
    for (int k = 0; k < Kk; k++) { dk[k] = __expf(dk[k] - mx); sum += dk[k]; }
    float inv = __fdividef(1.0f, sum);
#pragma unroll
    for (int k = 0; k < Kk; k++) dk[k] = fmaf(dk[k], inv, EPSF);

    if (wr && half == 0) {
        int n = n0 + t;
#pragma unroll
        for (int k = 0; k < Kk; k++)
            attn_out[((size_t)(b * Kk + k)) * Nn + n] = dk[k];
    }
    // s1/s2: count each token once (half==0 contributes)
#pragma unroll
    for (int k = 0; k < Kk; k++) {
        float s1v = half ? 0.f : dk[k];
        float s2v = half ? 0.f : dk[k] * rm;
#pragma unroll
        for (int o = 16; o; o >>= 1) {
            s1v += __shfl_xor_sync(~0u, s1v, o);
            s2v += __shfl_xor_sync(~0u, s2v, o);
        }
        if (lane == 0) {
            atomicAdd(&g_s1[b * Kk + k], s1v);
            atomicAdd(&g_s2[b * Kk + k], s2v);
        }
    }
    __syncthreads();  // all Ws reads done
    if (half == 0) {
#pragma unroll
        for (int k = 0; k < Kk; k++) A1[t * KP + k] = dk[k] * rs;
        A1[t * KP + 11] = 0.f;
    }
    __syncthreads();

    // phase C: units (d, token-half); 384 units over 256 threads
    float* Rb = g_R + b * Kk * Dd;
    for (int w = tid; w < 384; w += 256) {
        int h = (w >= 192) ? 1 : 0;
        int d = w - h * 192;
        ull c6[6];
#pragma unroll
        for (int j = 0; j < 6; j++) c6[j] = 0ull;
        int t0 = h * 64;
#pragma unroll 2
        for (int tt = t0; tt < t0 + 64; tt++) {
            fma12(c6, &A1[tt * KP], pk2(Xs[tt * XST + d]));
        }
#pragma unroll
        for (int j = 0; j < 6; j++) {
            float2 f = up2(c6[j]);
            atomicAdd(&Rb[(2 * j) * Dd + d], f.x);
            if (2 * j + 1 < Kk) atomicAdd(&Rb[(2 * j + 1) * Dd + d], f.y);
        }
    }
}

// ---------------- GRU ----------------
__global__ __launch_bounds__(288) void k_gru(const float* __restrict__ bv,
                                             const float* __restrict__ Wih,
                                             const float* __restrict__ Whh,
                                             const float* __restrict__ bih,
                                             const float* __restrict__ bhh,
                                             const float* __restrict__ lnw_in,
                                             const float* __restrict__ lnb_in) {
    __shared__ float uT[Dd * KP], spT[Dd * KP], vT[Dd * KP];
    __shared__ float P0[96 * KP], P1[96 * KP], PXn[96 * KP], PHn[96 * KP];
    __shared__ float sinv[Kk], s2s[Kk];
    int hh = blockIdx.x, b = blockIdx.y, tid = threadIdx.x;
    if (tid < Kk) {
        sinv[tid] = __fdividef(1.0f, g_s1[b * Kk + tid]);
        s2s[tid] = g_s2[b * Kk + tid];
    }
    __syncthreads();
    for (int i = tid; i < Dd; i += 288) { uT[i * KP + 11] = 0.f; spT[i * KP + 11] = 0.f; }
    for (int i = tid; i < Kk * Dd; i += 288) {
        int r = i / Dd, d = i - r * Dd;
        float R = g_R[b * Kk * Dd + i];
        uT[d * KP + r] = lnw_in[d] * (R - s2s[r]) * sinv[r] + lnb_in[d];
        spT[d * KP + r] = g_slots[b * Kk * Dd + i];
    }
    __syncthreads();
    if (tid < Dd) {
        ull a6[6];
#pragma unroll
        for (int j = 0; j < 6; j++) a6[j] = 0ull;
        const float4* w4 = (const float4*)(g_WvT + tid * Dd);
#pragma unroll 4
        for (int c = 0; c < 48; c++) {
            float4 w = __ldg(&w4[c]);
            fma12(a6, &uT[(4 * c + 0) * KP], pk2(w.x));
            fma12(a6, &uT[(4 * c + 1) * KP], pk2(w.y));
            fma12(a6, &uT[(4 * c + 2) * KP], pk2(w.z));
            fma12(a6, &uT[(4 * c + 3) * KP], pk2(w.w));
        }
        float vv[Kk];
        unpk11(a6, vv);
        float bvv = bv[tid];
#pragma unroll
        for (int r = 0; r < Kk; r++) vT[tid * KP + r] = vv[r] + bvv;
        vT[tid * KP + 11] = 0.f;
    }
    __syncthreads();
    int g = tid / 96, tl = tid - g * 96, t = hh * 96 + tl;
    int j = g * Dd + t;
    ull ax6[6], ah6[6];
#pragma unroll
    for (int jj = 0; jj < 6; jj++) { ax6[jj] = 0ull; ah6[jj] = 0ull; }
    const float4* wi4 = (const float4*)(Wih + j * Dd);
    const float4* wh4 = (const float4*)(Whh + j * Dd);
#pragma unroll 4
    for (int c = 0; c < 48; c++) {
        float4 wi = __ldg(&wi4[c]);
        float4 wh = __ldg(&wh4[c]);
        fma12(ax6, &vT[(4 * c + 0) * KP], pk2(wi.x));
        fma12(ax6, &vT[(4 * c + 1) * KP], pk2(wi.y));
        fma12(ax6, &vT[(4 * c + 2) * KP], pk2(wi.z));
        fma12(ax6, &vT[(4 * c + 3) * KP], pk2(wi.w));
        fma12(ah6, &spT[(4 * c + 0) * KP], pk2(wh.x));
        fma12(ah6, &spT[(4 * c + 1) * KP], pk2(wh.y));
        fma12(ah6, &spT[(4 * c + 2) * KP], pk2(wh.z));
        fma12(ah6, &spT[(4 * c + 3) * KP], pk2(wh.w));
    }
    float axf[Kk], ahf[Kk];
    unpk11(ax6, axf); unpk11(ah6, ahf);
    float bi = bih[j], bh = bhh[j];
    if (g == 0) {
#pragma unroll
        for (int r = 0; r < Kk; r++) P0[tl * KP + r] = axf[r] + ahf[r] + bi + bh;
    } else if (g == 1) {
#pragma unroll
        for (int r = 0; r < Kk; r++) P1[tl * KP + r] = axf[r] + ahf[r] + bi + bh;
    } else {
#pragma unroll
        for (int r = 0; r < Kk; r++) { PXn[tl * KP + r] = axf[r] + bi; PHn[tl * KP + r] = ahf[r] + bh; }
    }
    __syncthreads();
    for (int i = tid; i < Kk * 96; i += 288) {
        int r = i / 96, tl2 = i - r * 96, tg = hh * 96 + tl2;
        float rg = 1.0f / (1.0f + __expf(-P0[tl2 * KP + r]));
        float zg = 1.0f / (1.0f + __expf(-P1[tl2 * KP + r]));
        float ng = tanhf(fmaf(rg, PHn[tl2 * KP + r], PXn[tl2 * KP + r]));
        float hp = spT[tg * KP + r];
        g_h[(b * Kk + r) * Dd + tg] = (1.0f - zg) * ng + zg * hp;
    }
}

// ---------------- LN + MLP + residual ----------------
__global__ __launch_bounds__(192) void k_mlp(const float* __restrict__ lnw,
                                             const float* __restrict__ lnb,
                                             const float* __restrict__ b1,
                                             const float* __restrict__ b2,
                                             float* __restrict__ slots_out, int last) {
    __shared__ float hT[Dd * KP];
    __shared__ float m1T[HIDn * KP];
    int b = blockIdx.x, t = threadIdx.x, wid = t >> 5, lane = t & 31;
    hT[t * KP + 11] = 0.f;
    if (t < HIDn) m1T[t * KP + 11] = 0.f;
    for (int r = wid; r < Kk; r += 6) {
        float v[6], s = 0.f;
#pragma unroll
        for (int i = 0; i < 6; i++) { v[i] = g_h[(b * Kk + r) * Dd + lane + 32 * i]; s += v[i]; }
#pragma unroll
        for (int o = 16; o; o >>= 1) s += __shfl_xor_sync(~0u, s, o);
        float mu = s * (1.0f / Dd), q = 0.f;
#pragma unroll
        for (int i = 0; i < 6; i++) { float d = v[i] - mu; q += d * d; }
#pragma unroll
        for (int o = 16; o; o >>= 1) q += __shfl_xor_sync(~0u, q, o);
        float rstd = rsqrtf(q * (1.0f / Dd) + LN_EPSF);
#pragma unroll
        for (int i = 0; i < 6; i++) {
            int d = lane + 32 * i;
            hT[d * KP + r] = (v[i] - mu) * rstd * lnw[d] + lnb[d];
        }
    }
    __syncthreads();
    if (t < HIDn) {
        ull a6[6];
#pragma unroll
        for (int j = 0; j < 6; j++) a6[j] = 0ull;
        const float4* w4 = (const float4*)(g_W1T + t * Dd);
#pragma unroll 4
        for (int c = 0; c < 48; c++) {
            float4 w = __ldg(&w4[c]);
            fma12(a6, &hT[(4 * c + 0) * KP], pk2(w.x));
            fma12(a6, &hT[(4 * c + 1) * KP], pk2(w.y));
            fma12(a6, &hT[(4 * c + 2) * KP], pk2(w.z));
            fma12(a6, &hT[(4 * c + 3) * KP], pk2(w.w));
        }
        float vv[Kk];
        unpk11(a6, vv);
        float b1v = b1[t];
#pragma unroll
        for (int r = 0; r < Kk; r++) m1T[t * KP + r] = fmaxf(vv[r] + b1v, 0.0f);
    }
    __syncthreads();
    ull a6[6];
#pragma unroll
    for (int j = 0; j < 6; j++) a6[j] = 0ull;
    {
        const float4* w4 = (const float4*)(g_W2T + t * HIDn);
#pragma unroll 4
        for (int c = 0; c < 32; c++) {
            float4 w = __ldg(&w4[c]);
            fma12(a6, &m1T[(4 * c + 0) * KP], pk2(w.x));
            fma12(a6, &m1T[(4 * c + 1) * KP], pk2(w.y));
            fma12(a6, &m1T[(4 * c + 2) * KP], pk2(w.z));
            fma12(a6, &m1T[(4 * c + 3) * KP], pk2(w.w));
        }
    }
    float acc[Kk];
    unpk11(a6, acc);
    float b2v = b2[t];
#pragma unroll
    for (int r = 0; r < Kk; r++) {
        float o = g_h[(b * Kk + r) * Dd + t] + acc[r] + b2v;
        g_slots[(b * Kk + r) * Dd + t] = o;
        if (last) slots_out[(b * Kk + r) * Dd + t] = o;
    }
}

extern "C" void kernel_launch(void* const* d_in, const int* in_sizes, int n_in,
                              void* d_out, int out_size) {
    const float* inputs = (const float*)d_in[0];
    const float* noise = (const float*)d_in[1];
    const float* smu = (const float*)d_in[2];
    const float* ssig = (const float*)d_in[3];
    const float* ln_in_w = (const float*)d_in[4];
    const float* ln_in_b = (const float*)d_in[5];
    const float* ln_sl_w = (const float*)d_in[6];
    const float* ln_sl_b = (const float*)d_in[7];
    const float* ln_ml_w = (const float*)d_in[8];
    const float* ln_ml_b = (const float*)d_in[9];
    const float* Wq = (const float*)d_in[10];
    const float* bq = (const float*)d_in[11];
    const float* Wk = (const float*)d_in[12];
    const float* bk = (const float*)d_in[13];
    const float* Wv = (const float*)d_in[14];
    const float* bv = (const float*)d_in[15];
    const float* Wih = (const float*)d_in[16];
    const float* Whh = (const float*)d_in[17];
    const float* bih = (const float*)d_in[18];
    const float* bhh = (const float*)d_in[19];
    const float* W1 = (const float*)d_in[20];
    const float* b1 = (const float*)d_in[21];
    const float* W2 = (const float*)d_in[22];
    const float* b2 = (const float*)d_in[23];

    float* out = (float*)d_out;
    float* slots_out = out;
    float* attn_out = out + Bn * Kk * Dd;

    const int ATTN_SMEM = (Tt * XST + Kk * Dd) * 4;  // 108,800 bytes
    static bool attr_set = false;
    if (!attr_set) {
        cudaFuncSetAttribute(k_attn, cudaFuncAttributeMaxDynamicSharedMemorySize, ATTN_SMEM);
        attr_set = true;
    }

    k_init<<<384, 256>>>(noise, smu, ssig, Wq, Wv, W1, W2);
    for (int it = 0; it < 3; it++) {
        int last = (it == 2) ? 1 : 0;
        k_pre<<<Bn, 192>>>(ln_sl_w, ln_sl_b, bq, Wk, bk, ln_in_w, ln_in_b);
        k_attn<<<dim3(Nn / Tt, Bn), 256, ATTN_SMEM>>>(inputs, attn_out, last);
        k_gru<<<dim3(2, Bn), 288>>>(bv, Wih, Whh, bih, bhh, ln_in_w, ln_in_b);
        k_mlp<<<Bn, 192>>>(ln_ml_w, ln_ml_b, b1, b2, slots_out, last);
    }
}